// round 3
// baseline (speedup 1.0000x reference)
#include <cuda_runtime.h>

// PRNG variant: 2 = ORIGINAL (non-partitionable) threefry scheme + original split
//                   [env evidence: partitionable variants 0/3 both gave rel_err ~3e-3]
//               3 = partitionable (counter = u64 iota -> (hi,lo)), bits = y0 ^ y1  -> FAILED R2
//               0 = partitionable, bits = y1                                      -> FAILED R1
//               1 = partitionable, bits = y0
#define SCORE_VARIANT 2

typedef unsigned int u32;
typedef unsigned long long u64;

static const int HW    = 512 * 512;      // 262144
static const int NPIX  = 4 * HW;         // 1048576
static const int OUTCH = 256;
static const int PNUM  = 2048;           // POS_NUM * B
static const int TPTS  = 4096;
static const int NBUCK = 1024;
static const int CAND_MAX = 65536;

// ---------------- scratch (static device globals; no allocation) ----------------
__device__ u32 g_rec[NPIX];              // score23<<2 | pos<<1 | neg
__device__ u32 g_hist[2 * NBUCK];
__device__ int g_sel[TPTS];              // [0..2047] pos pixel idx, [2048..4095] neg
__device__ u64 g_cand[2][CAND_MAX];
__device__ int g_cnt[4];                 // selpos, selneg, candpos, candneg
__device__ int g_tb[2];
__device__ int g_need[2];
__device__ u32 g_keys[4];                // kp0,kp1,kn0,kn1
__device__ float g_G[16], g_u[4], g_beta;
__device__ float4 g_pf[TPTS];
__device__ float4 g_pg[TPTS];
__device__ float g_pc[TPTS];
__device__ float g_pinv[TPTS];
__device__ double g_sum;
__device__ u64 g_totcnt;

// ---------------- threefry2x32 (exact JAX cipher) ----------------
__device__ __forceinline__ uint2 tf2x32(u32 k0, u32 k1, u32 x0, u32 x1) {
    u32 ks2 = k0 ^ k1 ^ 0x1BD11BDAu;
    x0 += k0; x1 += k1;
#define TF_RND(r) { x0 += x1; x1 = __funnelshift_l(x1, x1, r); x1 ^= x0; }
    TF_RND(13) TF_RND(15) TF_RND(26) TF_RND(6)
    x0 += k1;  x1 += ks2 + 1u;
    TF_RND(17) TF_RND(29) TF_RND(16) TF_RND(24)
    x0 += ks2; x1 += k0 + 2u;
    TF_RND(13) TF_RND(15) TF_RND(26) TF_RND(6)
    x0 += k0;  x1 += k1 + 3u;
    TF_RND(17) TF_RND(29) TF_RND(16) TF_RND(24)
    x0 += k1;  x1 += ks2 + 4u;
    TF_RND(13) TF_RND(15) TF_RND(26) TF_RND(6)
    x0 += ks2; x1 += k0 + 5u;
#undef TF_RND
    return make_uint2(x0, x1);
}

__device__ __forceinline__ u32 score_bits(u32 k0, u32 k1, u32 e) {
#if SCORE_VARIANT == 0
    return tf2x32(k0, k1, 0u, e).y;
#elif SCORE_VARIANT == 1
    return tf2x32(k0, k1, 0u, e).x;
#elif SCORE_VARIANT == 3
    uint2 r = tf2x32(k0, k1, 0u, e);
    return r.x ^ r.y;
#else
    // original scheme: count vector iota(n) split into halves
    const u32 half = (u32)(NPIX / 2);
    if (e < half) return tf2x32(k0, k1, e, e + half).x;
    else          return tf2x32(k0, k1, e - half, e).y;
#endif
}

// ---------------- KZ: zero state + derive subkeys ----------------
__global__ void KZ() {
    int t = threadIdx.x;
    for (int i = t; i < 2 * NBUCK; i += blockDim.x) g_hist[i] = 0u;
    if (t < 4) g_cnt[t] = 0;
    if (t == 0) {
        g_sum = 0.0; g_totcnt = 0ull;
        g_tb[0] = g_tb[1] = 0; g_need[0] = g_need[1] = 0;
        // jax.random.key(42) -> (0, 42); split into kp (pos) and kn (neg)
#if SCORE_VARIANT == 2
        // original split: threefry_2x32(key, iota(4)) -> halves [0,1],[2,3]
        uint2 r0 = tf2x32(0u, 42u, 0u, 2u);
        uint2 r1 = tf2x32(0u, 42u, 1u, 3u);
        g_keys[0] = r0.x; g_keys[1] = r1.x;   // kp
        g_keys[2] = r0.y; g_keys[3] = r1.y;   // kn
#else
        // partitionable foldlike split: new key i = threefry(key, (0, i))
        uint2 a = tf2x32(0u, 42u, 0u, 0u);
        uint2 c = tf2x32(0u, 42u, 0u, 1u);
        g_keys[0] = a.x; g_keys[1] = a.y;     // kp
        g_keys[2] = c.x; g_keys[3] = c.y;     // kn
#endif
    }
}

// ---------------- KA: masks + scores + histogram ----------------
__global__ void KA(const float* __restrict__ pf, const float* __restrict__ pp,
                   const float* __restrict__ gt) {
    __shared__ u32 sh[2 * NBUCK];
    for (int i = threadIdx.x; i < 2 * NBUCK; i += blockDim.x) sh[i] = 0u;
    __syncthreads();
    u32 kp0 = g_keys[0], kp1 = g_keys[1], kn0 = g_keys[2], kn1 = g_keys[3];
    int base = blockIdx.x * (blockDim.x * 16);
    for (int it = 0; it < 16; it++) {
        int e = base + it * blockDim.x + threadIdx.x;
        int b = e >> 18, rem = e & (HW - 1);
        float v  = pf[b * HW + rem];
        float p0 = pp[(b * 3 + 0) * HW + rem];
        float p1 = pp[(b * 3 + 1) * HW + rem];
        float p2 = pp[(b * 3 + 2) * HW + rem];
        float gv = gt[b * HW + rem];
        bool region = (v >= 0.5f) && (p0 >= p1) && (p0 >= p2);
        u32 rec = 0u;
        if (region) {
            bool pos = gv > 0.5f;
            u32 bits = pos ? score_bits(kp0, kp1, (u32)e) : score_bits(kn0, kn1, (u32)e);
            u32 s23 = bits >> 9;                      // uniform-float ordering key
            rec = (s23 << 2) | (pos ? 2u : 1u);
            atomicAdd(&sh[(pos ? 0 : NBUCK) + (s23 >> 13)], 1u);
        }
        g_rec[e] = rec;
    }
    __syncthreads();
    for (int i = threadIdx.x; i < 2 * NBUCK; i += blockDim.x) {
        u32 x = sh[i];
        if (x) atomicAdd(&g_hist[i], x);
    }
}

// ---------------- KB: threshold buckets (suffix scan) + G,u,beta ----------------
__global__ void KB(const float* __restrict__ Wm, const float* __restrict__ bv) {
    __shared__ u32 s[NBUCK];
    int t = threadIdx.x;  // 1024 threads
    for (int side = 0; side < 2; side++) {
        s[t] = g_hist[side * NBUCK + t];
        __syncthreads();
        for (int off = 1; off < NBUCK; off <<= 1) {
            u32 v = s[t] + ((t + off < NBUCK) ? s[t + off] : 0u);
            __syncthreads();
            s[t] = v;
            __syncthreads();
        }
        u32 suf   = s[t];
        u32 above = (t < NBUCK - 1) ? s[t + 1] : 0u;
        if (suf >= (u32)PNUM && above < (u32)PNUM) {
            g_tb[side] = t;
            g_need[side] = PNUM - (int)above;
        }
        __syncthreads();
    }
    // warp 0: G = W^T W, u = W^T b, beta = b.b
    if (t < 32) {
        float G00=0,G01=0,G02=0,G03=0,G11=0,G12=0,G13=0,G22=0,G23=0,G33=0;
        float u0=0,u1=0,u2=0,u3=0,bb=0;
        for (int r = t; r < OUTCH; r += 32) {
            float w0 = Wm[r*4+0], w1 = Wm[r*4+1], w2 = Wm[r*4+2], w3 = Wm[r*4+3];
            float br = bv[r];
            G00 += w0*w0; G01 += w0*w1; G02 += w0*w2; G03 += w0*w3;
            G11 += w1*w1; G12 += w1*w2; G13 += w1*w3;
            G22 += w2*w2; G23 += w2*w3; G33 += w3*w3;
            u0 += w0*br; u1 += w1*br; u2 += w2*br; u3 += w3*br; bb += br*br;
        }
        for (int o = 16; o; o >>= 1) {
            G00 += __shfl_down_sync(0xFFFFFFFFu, G00, o);
            G01 += __shfl_down_sync(0xFFFFFFFFu, G01, o);
            G02 += __shfl_down_sync(0xFFFFFFFFu, G02, o);
            G03 += __shfl_down_sync(0xFFFFFFFFu, G03, o);
            G11 += __shfl_down_sync(0xFFFFFFFFu, G11, o);
            G12 += __shfl_down_sync(0xFFFFFFFFu, G12, o);
            G13 += __shfl_down_sync(0xFFFFFFFFu, G13, o);
            G22 += __shfl_down_sync(0xFFFFFFFFu, G22, o);
            G23 += __shfl_down_sync(0xFFFFFFFFu, G23, o);
            G33 += __shfl_down_sync(0xFFFFFFFFu, G33, o);
            u0 += __shfl_down_sync(0xFFFFFFFFu, u0, o);
            u1 += __shfl_down_sync(0xFFFFFFFFu, u1, o);
            u2 += __shfl_down_sync(0xFFFFFFFFu, u2, o);
            u3 += __shfl_down_sync(0xFFFFFFFFu, u3, o);
            bb += __shfl_down_sync(0xFFFFFFFFu, bb, o);
        }
        if (t == 0) {
            g_G[0]=G00; g_G[1]=G01; g_G[2]=G02; g_G[3]=G03;
            g_G[4]=G01; g_G[5]=G11; g_G[6]=G12; g_G[7]=G13;
            g_G[8]=G02; g_G[9]=G12; g_G[10]=G22; g_G[11]=G23;
            g_G[12]=G03; g_G[13]=G13; g_G[14]=G23; g_G[15]=G33;
            g_u[0]=u0; g_u[1]=u1; g_u[2]=u2; g_u[3]=u3;
            g_beta = bb;
        }
    }
}

// ---------------- KC: collect definite selections + boundary candidates ----------------
__global__ void KC() {
    int tbp = g_tb[0], tbn = g_tb[1];
    int base = blockIdx.x * (blockDim.x * 16);
    for (int it = 0; it < 16; it++) {
        int e = base + it * blockDim.x + threadIdx.x;
        u32 rec = g_rec[e];
        u32 fl = rec & 3u;
        if (!fl) continue;
        u32 s23 = rec >> 2;
        int side = (fl == 2u) ? 0 : 1;
        int tb = side ? tbn : tbp;
        int bk = (int)(s23 >> 13);
        if (bk > tb) {
            int p = atomicAdd(&g_cnt[side], 1);
            g_sel[side * PNUM + p] = e;
        } else if (bk == tb) {
            int p = atomicAdd(&g_cnt[2 + side], 1);
            if (p < CAND_MAX)
                g_cand[side][p] = ((u64)s23 << 32) | (u32)(0xFFFFFFFFu - (u32)e);
        }
    }
}

// ---------------- KD: rank boundary candidates (score desc, index asc) ----------------
__global__ void KD() {
    int side = blockIdx.x;
    int n = g_cnt[2 + side];
    if (n > CAND_MAX) n = CAND_MAX;
    int need = g_need[side];
    const u64* cd = g_cand[side];
    for (int ci = threadIdx.x; ci < n; ci += blockDim.x) {
        u64 mk = cd[ci];
        int r = 0;
        for (int k = 0; k < n; k++) r += (cd[k] > mk) ? 1 : 0;
        if (r < need) {
            int p = atomicAdd(&g_cnt[side], 1);
            g_sel[side * PNUM + p] = (int)(0xFFFFFFFFu - (u32)mk);
        }
    }
}

// ---------------- KE: per-point precompute ----------------
__global__ void KE(const float* __restrict__ d1) {
    int i = blockIdx.x * blockDim.x + threadIdx.x;  // 0..4095
    int e = g_sel[i];
    int b = e >> 18, rem = e & (HW - 1);
    float f0 = d1[(b * 4 + 0) * HW + rem];
    float f1 = d1[(b * 4 + 1) * HW + rem];
    float f2 = d1[(b * 4 + 2) * HW + rem];
    float f3 = d1[(b * 4 + 3) * HW + rem];
    float u0 = g_u[0], u1 = g_u[1], u2 = g_u[2], u3 = g_u[3];
    float gg0 = g_G[0]*f0 + g_G[1]*f1 + g_G[2]*f2 + g_G[3]*f3 + u0;
    float gg1 = g_G[4]*f0 + g_G[5]*f1 + g_G[6]*f2 + g_G[7]*f3 + u1;
    float gg2 = g_G[8]*f0 + g_G[9]*f1 + g_G[10]*f2 + g_G[11]*f3 + u2;
    float gg3 = g_G[12]*f0 + g_G[13]*f1 + g_G[14]*f2 + g_G[15]*f3 + u3;
    float c = u0*f0 + u1*f1 + u2*f2 + u3*f3 + g_beta;
    float nsq = gg0*f0 + gg1*f1 + gg2*f2 + gg3*f3 + c;   // ||proj||^2
    nsq = fmaxf(nsq, 0.f);
    float nrm = fmaxf(sqrtf(nsq), 1e-8f);
    float inv = 1.0f / nrm;
    float sc = inv * 10.0f;                               // fold inv_i / TAU
    g_pf[i] = make_float4(f0, f1, f2, f3);
    g_pg[i] = make_float4(gg0 * sc, gg1 * sc, gg2 * sc, gg3 * sc);
    g_pc[i] = c * sc;
    g_pinv[i] = inv;
}

// ---------------- KF: pairwise loss ----------------
__global__ void KF() {
    const int i = blockIdx.x * 128 + threadIdx.x;
    const float4 gi = g_pg[i];
    const float ci = g_pc[i];
    const bool ipos = (i < PNUM);
    __shared__ float4 sf[128];
    __shared__ float si[128];
    double dsum = 0.0;
    u32 cnt = 0;
    const int j0 = blockIdx.y * 256;
    for (int jt = 0; jt < 256; jt += 128) {
        const int jb = j0 + jt;
        {
            const int j = jb + threadIdx.x;
            sf[threadIdx.x] = g_pf[j];
            si[threadIdx.x] = g_pinv[j];
        }
        __syncthreads();
        const bool same = (ipos == (jb < PNUM));
        float fsum = 0.f;
        #pragma unroll 8
        for (int k = 0; k < 128; k++) {
            const float4 f = sf[k];
            float s = ((gi.x * f.x + gi.y * f.y) + (gi.z * f.z + gi.w * f.w) + ci) * si[k];
            float l;
            if (same) { float t2 = fmaxf(0.5f - s, 0.f); l = t2 * t2; }
            else      { l = s * s; }
            if (jb + k == i) l = 0.f;
            fsum += l;
            cnt += (l != 0.f) ? 1u : 0u;
        }
        dsum += (double)fsum;
        __syncthreads();
    }
    __shared__ double rs[128];
    __shared__ u32 rc[128];
    rs[threadIdx.x] = dsum; rc[threadIdx.x] = cnt;
    __syncthreads();
    for (int o = 64; o; o >>= 1) {
        if (threadIdx.x < o) {
            rs[threadIdx.x] += rs[threadIdx.x + o];
            rc[threadIdx.x] += rc[threadIdx.x + o];
        }
        __syncthreads();
    }
    if (threadIdx.x == 0) {
        atomicAdd(&g_sum, rs[0]);
        atomicAdd(&g_totcnt, (u64)rc[0]);
    }
}

// ---------------- KG: finalize ----------------
__global__ void KG(float* out) {
    out[0] = (float)(g_sum / (double)g_totcnt);
}

extern "C" void kernel_launch(void* const* d_in, const int* in_sizes, int n_in,
                              void* d_out, int out_size) {
    const float* d1 = (const float*)d_in[0];
    const float* pf = (const float*)d_in[1];
    const float* pp = (const float*)d_in[2];
    const float* gt = (const float*)d_in[3];
    const float* Wm = (const float*)d_in[4];
    const float* bv = (const float*)d_in[5];
    float* out = (float*)d_out;

    KZ<<<1, 1024>>>();
    KA<<<256, 256>>>(pf, pp, gt);
    KB<<<1, 1024>>>(Wm, bv);
    KC<<<256, 256>>>();
    KD<<<2, 1024>>>();
    KE<<<16, 256>>>(d1);
    KF<<<dim3(32, 16), 128>>>();
    KG<<<1, 1>>>(out);
}